// round 10
// baseline (speedup 1.0000x reference)
#include <cuda_runtime.h>
#include <math.h>

// ----------------------------------------------------------------------------
// DSimilarity gradgrad: out[3i+a, 3j+b] = sum_{p: i1[p]=i, q: i2[q]=j}
//    gg(d1[p]-d2[q]) * u1[p,a] * u2[q,b]
// gg(x) = (inv_l2 - x^2 inv_l2^2) * exp(-0.5 x^2 inv_l2)
//
// k_prep    : deterministic counting sort; grid=2 (one block per array).
// k_compute : 16x16 atom tile per block; bucket rows staged (<=SMAXC entries)
//             into zero-padded shared memory; warp-uniform trip counts;
//             single-wave residency via __launch_bounds__(256,7).
// ----------------------------------------------------------------------------

#define MAX_ATOMS  4096
#define MAXC       64          // global bucket capacity
#define SMAXC      40          // staged-in-smem capacity (overflow -> global)
#define PREP_WARPS 8
#define TI         16
#define TJ         16

__device__ int    g_na1;
__device__ int    g_na2;
__device__ int    g_cnt1[MAX_ATOMS];
__device__ int    g_cnt2[MAX_ATOMS];
__device__ float4 g_pair1[MAX_ATOMS * MAXC];   // (d, ux, uy, uz) bucketed by i1
__device__ float4 g_pair2[MAX_ATOMS * MAXC];   // bucketed by i2

// ---- K1: deterministic bucket build. Two blocks, 512 threads each. ----
__global__ void __launch_bounds__(512)
k_prep(const float* __restrict__ d1, const float* __restrict__ u1,
       const int* __restrict__ i1,
       const float* __restrict__ d2, const float* __restrict__ u2,
       const int* __restrict__ i2,
       int n, const int* na1p, const int* na2p, int out_size) {
    extern __shared__ unsigned int hist[];   // [PREP_WARPS][MAX_ATOMS]

    int tid = threadIdx.x;
    int arr = blockIdx.x;                    // 0 or 1

    const float* dd   = arr ? d2 : d1;
    const float* uu   = arr ? u2 : u1;
    const int*   ii   = arr ? i2 : i1;
    int*         gcnt = arr ? g_cnt2 : g_cnt1;
    float4*      gp   = arr ? g_pair2 : g_pair1;

    if (arr == 0 && tid == 0) {
        int na1, na2;
        if (na1p != nullptr && na2p != nullptr) {
            na1 = *na1p;
            na2 = *na2p;
        } else {
            int tot = out_size / 9;
            int r = (int)(sqrtf((float)tot) + 0.5f);
            while (r > 0 && r * r > tot) r--;
            while ((r + 1) * (r + 1) <= tot) r++;
            na1 = r; na2 = r;
        }
        if (na1 < 1) na1 = 1;  if (na1 > MAX_ATOMS) na1 = MAX_ATOMS;
        if (na2 < 1) na2 = 1;  if (na2 > MAX_ATOMS) na2 = MAX_ATOMS;
        g_na1 = na1;
        g_na2 = na2;
    }

    for (int t = tid; t < PREP_WARPS * MAX_ATOMS; t += 512) hist[t] = 0u;
    __syncthreads();

    int wid  = tid >> 5;
    int lane = tid & 31;
    int range = (n + PREP_WARPS - 1) / PREP_WARPS;
    int start = wid * range;
    int end   = start + range; if (end > n) end = n;

    // Phase 1: per-warp histograms (order-independent atomics)
    if (wid < PREP_WARPS) {
        unsigned int* h = &hist[wid * MAX_ATOMS];
        for (int p0 = start; p0 < end; p0 += 32) {
            int p = p0 + lane;
            if (p < end) {
                unsigned a = (unsigned)ii[p];
                if (a < MAX_ATOMS) atomicAdd(&h[a], 1u);
            }
        }
    }
    __syncthreads();

    // Phase 2: exclusive prefix across warps per atom; totals to gcnt
    for (int atom = tid; atom < MAX_ATOMS; atom += 512) {
        unsigned run = 0;
        #pragma unroll
        for (int w = 0; w < PREP_WARPS; w++) {
            unsigned v = hist[w * MAX_ATOMS + atom];
            hist[w * MAX_ATOMS + atom] = run;
            run += v;
        }
        gcnt[atom] = (int)run;
    }
    __syncthreads();

    // Phase 3: deterministic placement (stable = ascending p)
    if (wid < PREP_WARPS) {
        unsigned int* h = &hist[wid * MAX_ATOMS];
        for (int p0 = start; p0 < end; p0 += 32) {
            int p = p0 + lane;
            bool act = (p < end);
            int a = act ? ii[p] : -1;
            if ((unsigned)a >= MAX_ATOMS) a = -1;
            unsigned peers = __match_any_sync(0xFFFFFFFFu, a);
            unsigned lower = peers & ((1u << lane) - 1u);
            int rank = __popc(lower);
            int slot = -1;
            if (a >= 0) slot = (int)h[a] + rank;
            __syncwarp();
            if (a >= 0 && lower == 0u) h[a] += (unsigned)__popc(peers);
            __syncwarp();
            if (a >= 0 && slot < MAXC) {
                gp[a * MAXC + slot] =
                    make_float4(dd[p], uu[3 * p + 0], uu[3 * p + 1], uu[3 * p + 2]);
            }
        }
    }
}

// ---- K2: fused compute. Block = 16x16 atom tile. ----
// Smem rows stride SMAXC+1 = 41 float4 (164 words = 4 mod 32 banks):
// LDS.128 phases hit banks {4tx..4tx+3} for tx 0..7 -> conflict-free.
// Rows zero-filled, loops run to warp-uniform max counts: padded entries
// have u=0 so they contribute exactly 0. Counts > SMAXC take a rare
// global-memory slow path.
__global__ void __launch_bounds__(TI * TJ, 7)
k_compute(const float* __restrict__ ls, float* __restrict__ out) {
    __shared__ float4 sP[TI][SMAXC + 1];
    __shared__ float4 sQ[TJ][SMAXC + 1];
    __shared__ int    sc1[TI];
    __shared__ int    sc2[TJ];

    int na1 = g_na1;
    int na2 = g_na2;
    int tiles_j = (na2 + TJ - 1) / TJ;
    int tiles_i = (na1 + TI - 1) / TI;
    int tile = blockIdx.x;
    if (tile >= tiles_i * tiles_j) return;
    int tile_i = tile / tiles_j;
    int tile_j = tile - tile_i * tiles_j;
    int ib = tile_i * TI;
    int jb = tile_j * TJ;

    int tid = threadIdx.x;

    // zero-fill both staging arrays (pads must read as exact zeros)
    {
        float4 z = make_float4(0.f, 0.f, 0.f, 0.f);
        float4* flat = &sP[0][0];
        const int tot4 = 2 * TI * (SMAXC + 1);     // sP and sQ are contiguous
        for (int t = tid; t < tot4; t += TI * TJ) flat[t] = z;
    }
    if (tid < TI) {
        int ii = ib + tid;
        int c = (ii < na1) ? g_cnt1[ii] : 0;
        sc1[tid] = (c > MAXC) ? MAXC : c;
    } else if (tid < TI + TJ) {
        int jj = jb + (tid - TI);
        int c = (jj < na2) ? g_cnt2[jj] : 0;
        sc2[tid - TI] = (c > MAXC) ? MAXC : c;
    }
    __syncthreads();

    int r = tid >> 4;
    int s = tid & 15;
    {
        int c1r = sc1[r]; if (c1r > SMAXC) c1r = SMAXC;
        int c2r = sc2[r]; if (c2r > SMAXC) c2r = SMAXC;
        for (int sl = s; sl < c1r; sl += 16) sP[r][sl] = g_pair1[(ib + r) * MAXC + sl];
        for (int sl = s; sl < c2r; sl += 16) sQ[r][sl] = g_pair2[(jb + r) * MAXC + sl];
    }
    __syncthreads();

    int tx = tid & 15;               // j within tile
    int ty = tid >> 4;               // i within tile
    int i = ib + ty;
    int j = jb + tx;

    float l = ls[0];
    float inv_l2 = 1.0f / (l * l);
    float cc    = -0.72134752f * inv_l2;      // -0.5 * log2(e) * inv_l2
    float minv4 = -inv_l2 * inv_l2;

    int c1 = sc1[ty];
    int c2 = sc2[tx];
    int c1s = (c1 > SMAXC) ? SMAXC : c1;
    int c2s = (c2 > SMAXC) ? SMAXC : c2;
    // warp-uniform staged bounds (padded entries contribute 0)
    int c1m = __reduce_max_sync(0xFFFFFFFFu, c1s);
    int c2m = __reduce_max_sync(0xFFFFFFFFu, c2s);

    float a00 = 0.f, a01 = 0.f, a02 = 0.f;
    float a10 = 0.f, a11 = 0.f, a12 = 0.f;
    float a20 = 0.f, a21 = 0.f, a22 = 0.f;

    for (int a = 0; a < c1m; a++) {
        float4 pa = sP[ty][a];
        float vx = 0.f, vy = 0.f, vz = 0.f;
        #pragma unroll 4
        for (int b = 0; b < c2m; b++) {
            float4 qb = sQ[tx][b];
            float diff = pa.x - qb.x;
            float d2s  = diff * diff;
            float ex;
            asm("ex2.approx.f32 %0, %1;" : "=f"(ex) : "f"(cc * d2s));
            float w = fmaf(d2s, minv4, inv_l2);   // inv_l2 - d2s*inv_l2^2
            float g = w * ex;
            vx += g * qb.y;
            vy += g * qb.z;
            vz += g * qb.w;
        }
        a00 += pa.y * vx; a01 += pa.y * vy; a02 += pa.y * vz;
        a10 += pa.z * vx; a11 += pa.z * vy; a12 += pa.z * vz;
        a20 += pa.w * vx; a21 += pa.w * vy; a22 += pa.w * vz;
    }

    // Rare overflow path: combos with a >= SMAXC or b >= SMAXC, from global.
    if (__any_sync(0xFFFFFFFFu, (c1 > SMAXC) | (c2 > SMAXC))) {
        if ((c1 > SMAXC || c2 > SMAXC) && i < na1 && j < na2) {
            const float4* __restrict__ GP = &g_pair1[i * MAXC];
            const float4* __restrict__ GQ = &g_pair2[j * MAXC];
            for (int a = 0; a < c1; a++) {
                float4 pa = (a < SMAXC) ? sP[ty][a] : GP[a];
                int b0 = (a < c1s) ? c2s : 0;   // staged region already summed
                float vx = 0.f, vy = 0.f, vz = 0.f;
                for (int b = b0; b < c2; b++) {
                    float4 qb = (b < SMAXC) ? sQ[tx][b] : GQ[b];
                    float diff = pa.x - qb.x;
                    float d2s  = diff * diff;
                    float ex;
                    asm("ex2.approx.f32 %0, %1;" : "=f"(ex) : "f"(cc * d2s));
                    float w = fmaf(d2s, minv4, inv_l2);
                    float g = w * ex;
                    vx += g * qb.y;
                    vy += g * qb.z;
                    vz += g * qb.w;
                }
                a00 += pa.y * vx; a01 += pa.y * vy; a02 += pa.y * vz;
                a10 += pa.z * vx; a11 += pa.z * vy; a12 += pa.z * vz;
                a20 += pa.w * vx; a21 += pa.w * vy; a22 += pa.w * vz;
            }
        }
    }

    if (i < na1 && j < na2) {
        int ld = 3 * na2;
        float* o0 = out + (3 * i + 0) * (long long)ld + 3 * j;
        float* o1 = o0 + ld;
        float* o2 = o1 + ld;
        o0[0] = a00; o0[1] = a01; o0[2] = a02;
        o1[0] = a10; o1[1] = a11; o1[2] = a12;
        o2[0] = a20; o2[1] = a21; o2[2] = a22;
    }
}

// ----------------------------------------------------------------------------
// Inputs (metadata order): d1[N], u1[N*3], d2[N], u2[N*3], lengthscale[1],
//                          i1[N], i2[N], [natoms1], [natoms2]
// Output: float[natoms1*3 * natoms2*3]
// ----------------------------------------------------------------------------
extern "C" void kernel_launch(void* const* d_in, const int* in_sizes, int n_in,
                              void* d_out, int out_size) {
    const float* d1 = (const float*)d_in[0];
    const float* u1 = (const float*)d_in[1];
    const float* d2 = (const float*)d_in[2];
    const float* u2 = (const float*)d_in[3];
    const float* ls = (const float*)d_in[4];
    const int*   i1 = (const int*)d_in[5];
    const int*   i2 = (const int*)d_in[6];
    const int*   na1p = (n_in >= 9) ? (const int*)d_in[7] : nullptr;
    const int*   na2p = (n_in >= 9) ? (const int*)d_in[8] : nullptr;

    int n_pairs = in_sizes[0];          // element count of d1 == N_PAIRS
    int tot = out_size / 9;             // na1 * na2

    // Tile-count upper bound for any (na1, na2) with na1*na2 = tot, na<=4096:
    int max_tiles = (tot + TI * TJ - 1) / (TI * TJ) + 2 * MAX_ATOMS / 16 + 2;

    int prep_smem = PREP_WARPS * MAX_ATOMS * (int)sizeof(unsigned int);
    cudaFuncSetAttribute(k_prep, cudaFuncAttributeMaxDynamicSharedMemorySize,
                         prep_smem);

    k_prep<<<2, 512, prep_smem>>>(d1, u1, i1, d2, u2, i2,
                                  n_pairs, na1p, na2p, out_size);
    k_compute<<<max_tiles, TI * TJ>>>(ls, (float*)d_out);
}